// round 15
// baseline (speedup 1.0000x reference)
#include <cuda_runtime.h>

// SpatialTransformer 3D trilinear resample. B=4, H=W=D=128, C=2, fp32.
//
// R14 = R13 + x-corner-pair merge WITHOUT data selects:
//  - per corner, ONE aligned LDG.128 window q=[v(xe),v(xe+1)], xe=x0&~1,
//    plus a predicated LDG.64 extra at x0+1 only for (x0 odd && dx) lanes
//  - x-interp folded into 3 coefficients (cLo,cHi,cEx) from parity/dx —
//    computed once per point, applied per corner: no per-element selects
//    (this removes R5's ALU explosion that killed the first merge attempt)
//  - stage holds payloads only (24 regs); px/py/pz recomputed bit-identically
//    in the math phase; 2-deep pipeline; launch_bounds(256,4)
//  - lane varies j (x): near-coalesced gathers; smem 32x33 transpose tile;
//    store phase lane varies k: coalesced 256B STG
//
// Reference conventions reproduced exactly: full-extent pixel mapping,
// clip-then-float corners, flat index y*W + z*W*H + x, far-slab weight
// (z1f - z0f). Edge cases (x0=0 dx=0, x0=127 dx=0) produce exact zeros,
// matching the reference's exact cancellation.

#define HH 128
#define WW 128
#define DD 128
#define NPB (HH * WW * DD)      // 2097152

struct Stage {
    float4 q00, q10, q01, q11;   // [xe, xe+1] windows for the 4 (y,z) corners
    float2 e00, e10, e01, e11;   // extras at x0+1 (only valid when odd && dx)
};

__device__ __forceinline__ void coords(
    float t2, float t6, float t10,
    float cx, float cy, float cz,
    int k0, int kl,
    float& px, float& py, float& pz)
{
    const float s = 2.0f / 127.0f;
    const float zg = fmaf((float)(k0 + kl), s, -1.0f);
    px = (fmaf(t2,  zg, cx) + 1.0f) * 64.0f;
    py = (fmaf(t6,  zg, cy) + 1.0f) * 64.0f;
    pz = (fmaf(t10, zg, cz) + 1.0f) * 64.0f;
}

__device__ __forceinline__ void stage_load(
    const float2* __restrict__ im2,
    float t2, float t6, float t10,
    float cx, float cy, float cz,
    int k0, int kl, Stage& sg)
{
    float px, py, pz;
    coords(t2, t6, t10, cx, cy, cz, k0, kl, px, py, pz);

    const int fx = __float2int_rd(px);
    const int fy = __float2int_rd(py);
    const int fz = __float2int_rd(pz);

    const int x0 = min(max(fx,     0), WW - 1);
    const int x1 = min(max(fx + 1, 0), WW - 1);
    const int y0 = min(max(fy,     0), HH - 1);
    const int y1 = min(max(fy + 1, 0), HH - 1);
    const int z0 = min(max(fz,     0), DD - 1);
    const int z1 = min(max(fz + 1, 0), DD - 1);

    // reference flat convention: y*W + z*(W*H) + x
    const int r00 = y0 * WW + z0 * (WW * HH);
    const int dy  = (y1 - y0) * WW;
    const int dz  = (z1 - z0) * (WW * HH);
    const int xe  = x0 & ~1;             // 16B-aligned window start

    sg.q00 = __ldg((const float4*)(im2 + r00 + xe));
    sg.q10 = __ldg((const float4*)(im2 + r00 + dy + xe));
    sg.q01 = __ldg((const float4*)(im2 + r00 + dz + xe));
    sg.q11 = __ldg((const float4*)(im2 + r00 + dy + dz + xe));

    const bool need = (x0 & 1) && (x1 != x0);
    if (need) {
        const float2* p = im2 + r00 + x0 + 1;
        sg.e00 = __ldg(p);
        sg.e10 = __ldg(p + dy);
        sg.e01 = __ldg(p + dz);
        sg.e11 = __ldg(p + dy + dz);
    } else {
        sg.e00 = make_float2(0.0f, 0.0f);
        sg.e10 = make_float2(0.0f, 0.0f);
        sg.e01 = make_float2(0.0f, 0.0f);
        sg.e11 = make_float2(0.0f, 0.0f);
    }
}

__device__ __forceinline__ float2 stage_math(
    const Stage& sg,
    float t2, float t6, float t10,
    float cx, float cy, float cz,
    int k0, int kl)
{
    float px, py, pz;
    coords(t2, t6, t10, cx, cy, cz, k0, kl, px, py, pz);  // bit-identical to load phase

    const float fxf = floorf(px);
    const float fyf = floorf(py);
    const float fzf = floorf(pz);

    const float x0f = fminf(fmaxf(fxf,        0.0f), 127.0f);
    const float x1f = fminf(fmaxf(fxf + 1.0f, 0.0f), 127.0f);
    const float y0f = fminf(fmaxf(fyf,        0.0f), 127.0f);
    const float y1f = fminf(fmaxf(fyf + 1.0f, 0.0f), 127.0f);
    const float z0f = fminf(fmaxf(fzf,        0.0f), 127.0f);
    const float z1f = fminf(fmaxf(fzf + 1.0f, 0.0f), 127.0f);

    const float wx1 = x1f - px, wx0 = px - x0f;
    const float wy1 = y1f - py, wy0 = py - y0f;
    const float wzA = z1f - pz;            // near slab (z1f - z)
    const float wzB = z1f - z0f;           // far slab  (z1f - z0f) — ref convention

    // x-interp coefficients over {q.lo, q.hi, extra}
    const int  x0i = (int)x0f;
    const bool odd = (x0i & 1);
    const bool dx  = (x1f != x0f);
    const float sum0 = dx ? wx1 : (wx1 + wx0);   // coeff on slot x0
    const float sum1 = dx ? wx0 : 0.0f;          // coeff on slot x0+1
    const float cLo = odd ? 0.0f : sum0;
    const float cHi = odd ? sum0 : sum1;
    const float cEx = odd ? sum1 : 0.0f;

    // per-corner x-interp
    const float i00x = fmaf(cLo, sg.q00.x, fmaf(cHi, sg.q00.z, cEx * sg.e00.x));
    const float i00y = fmaf(cLo, sg.q00.y, fmaf(cHi, sg.q00.w, cEx * sg.e00.y));
    const float i10x = fmaf(cLo, sg.q10.x, fmaf(cHi, sg.q10.z, cEx * sg.e10.x));
    const float i10y = fmaf(cLo, sg.q10.y, fmaf(cHi, sg.q10.w, cEx * sg.e10.y));
    const float i01x = fmaf(cLo, sg.q01.x, fmaf(cHi, sg.q01.z, cEx * sg.e01.x));
    const float i01y = fmaf(cLo, sg.q01.y, fmaf(cHi, sg.q01.w, cEx * sg.e01.y));
    const float i11x = fmaf(cLo, sg.q11.x, fmaf(cHi, sg.q11.z, cEx * sg.e11.x));
    const float i11y = fmaf(cLo, sg.q11.y, fmaf(cHi, sg.q11.w, cEx * sg.e11.y));

    float2 r;
    r.x = wzA * fmaf(wy1, i00x, wy0 * i10x) + wzB * fmaf(wy1, i01x, wy0 * i11x);
    r.y = wzA * fmaf(wy1, i00y, wy0 * i10y) + wzB * fmaf(wy1, i01y, wy0 * i11y);
    return r;
}

__global__ __launch_bounds__(256, 4) void st3d_kernel(
    const float* __restrict__ image,   // [B, H, W, D, C] flat, C=2
    const float* __restrict__ theta,   // [B, 3, 4]
    float2* __restrict__ out)          // [B*N] float2
{
    __shared__ float2 tile[32][33];

    const int tid  = threadIdx.x;
    const int lane = tid & 31;
    const int wid  = tid >> 5;

    // grid: 4 k-tiles * 4 j-tiles * 128 i * 4 b = 8192 blocks
    const unsigned bx = blockIdx.x;
    const int k0 = (bx & 3) << 5;
    const int j0 = ((bx >> 2) & 3) << 5;
    const int i  = (bx >> 4) & 127;
    const int b  = bx >> 11;

    const float* t = theta + b * 12;
    const float t0  = __ldg(t + 0),  t1  = __ldg(t + 1),  t2  = __ldg(t + 2),  t3  = __ldg(t + 3);
    const float t4  = __ldg(t + 4),  t5  = __ldg(t + 5),  t6  = __ldg(t + 6),  t7  = __ldg(t + 7);
    const float t8  = __ldg(t + 8),  t9  = __ldg(t + 9),  t10 = __ldg(t + 10), t11 = __ldg(t + 11);

    const float s = 2.0f / 127.0f;
    const float xg = fmaf((float)(j0 + lane), s, -1.0f);   // lane varies x
    const float yg = fmaf((float)i, s, -1.0f);

    const float cx = fmaf(t0, xg, fmaf(t1, yg, t3));
    const float cy = fmaf(t4, xg, fmaf(t5, yg, t7));
    const float cz = fmaf(t8, xg, fmaf(t9, yg, t11));

    const float2* __restrict__ im2 = (const float2*)image + (size_t)b * NPB;

    // 2-deep software pipeline over the 4 k-iterations (kl = wid + 8*it)
    Stage s0, s1;
    stage_load(im2, t2, t6, t10, cx, cy, cz, k0, wid,      s0);
    stage_load(im2, t2, t6, t10, cx, cy, cz, k0, wid + 8,  s1);

    tile[lane][wid]      = stage_math(s0, t2, t6, t10, cx, cy, cz, k0, wid);
    stage_load(im2, t2, t6, t10, cx, cy, cz, k0, wid + 16, s0);

    tile[lane][wid + 8]  = stage_math(s1, t2, t6, t10, cx, cy, cz, k0, wid + 8);
    stage_load(im2, t2, t6, t10, cx, cy, cz, k0, wid + 24, s1);

    tile[lane][wid + 16] = stage_math(s0, t2, t6, t10, cx, cy, cz, k0, wid + 16);
    tile[lane][wid + 24] = stage_math(s1, t2, t6, t10, cx, cy, cz, k0, wid + 24);

    __syncthreads();

    // store phase: lane varies k -> coalesced 256B warp stores
    float2* __restrict__ op = out + (size_t)b * NPB + i * (WW * DD) + j0 * DD + k0;
    #pragma unroll
    for (int it = 0; it < 4; it++) {
        const int jl = wid + 8 * it;
        op[jl * DD + lane] = tile[jl][lane];
    }
}

extern "C" void kernel_launch(void* const* d_in, const int* in_sizes, int n_in,
                              void* d_out, int out_size) {
    const float* image = (const float*)d_in[0];
    const float* theta = (const float*)d_in[1];
    float2* out = (float2*)d_out;

    st3d_kernel<<<8192, 256>>>(image, theta, out);
}

// round 16
// speedup vs baseline: 1.1673x; 1.1673x over previous
#include <cuda_runtime.h>

// SpatialTransformer 3D trilinear resample. B=4, H=W=D=128, C=2, fp32.
//
// R16 = R13 (best, 53.8us) + two L1-offload tweaks:
//  - theta staged into __constant__ memory via cudaMemcpyToSymbolAsync (D2D,
//    graph-capturable): theta reads become constant-port LDC (uniform per
//    block), removing ~96 L1 wavefronts/block (~7% of L1 traffic)
//  - store phase at float4 granularity (LDS.128 + STG.128): same wavefronts,
//    half the instructions
// Gather structure unchanged from R13: 2-deep pipeline, 16 LDG.64 in flight,
// slim Stage (payloads + px/py/pz), launch_bounds(256,5) -> 48-reg cap,
// lane varies j (x) for near-coalesced gathers, smem 32x33 transpose tile.
//
// Reference conventions reproduced exactly: full-extent pixel mapping,
// clip-then-float corners, flat index y*W + z*W*H + x, far-slab weight
// (z1f - z0f). Numerics identical to R13 (rel_err 5.270149e-4).

#define HH 128
#define WW 128
#define DD 128
#define NPB (HH * WW * DD)      // 2097152

__constant__ float c_theta[48];   // 4 batches x 12

struct Stage {
    float2 pa, pb, pc, pd, pe, pf, pg, ph;
    float px, py, pz;
};

__device__ __forceinline__ void stage_load(
    const float2* __restrict__ im2,
    float t2, float t6, float t10,
    float cx, float cy, float cz,
    int k0, int kl, Stage& sg)
{
    const float s = 2.0f / 127.0f;
    const float zg = fmaf((float)(k0 + kl), s, -1.0f);

    const float px = (fmaf(t2,  zg, cx) + 1.0f) * 64.0f;
    const float py = (fmaf(t6,  zg, cy) + 1.0f) * 64.0f;
    const float pz = (fmaf(t10, zg, cz) + 1.0f) * 64.0f;
    sg.px = px; sg.py = py; sg.pz = pz;

    const int fx = __float2int_rd(px);
    const int fy = __float2int_rd(py);
    const int fz = __float2int_rd(pz);

    const int x0 = min(max(fx,     0), WW - 1);
    const int x1 = min(max(fx + 1, 0), WW - 1);
    const int y0 = min(max(fy,     0), HH - 1);
    const int y1 = min(max(fy + 1, 0), HH - 1);
    const int z0 = min(max(fz,     0), DD - 1);
    const int z1 = min(max(fz + 1, 0), DD - 1);

    // reference flat convention: y*W + z*(W*H) + x
    const int p00 = y0 * WW + z0 * (WW * HH) + x0;
    const int dx  = x1 - x0;
    const int dy  = (y1 - y0) * WW;
    const int dz  = (z1 - z0) * (WW * HH);

    const float2* a = im2 + p00;
    sg.pa = __ldg(a);
    sg.pc = __ldg(a + dx);
    sg.pb = __ldg(a + dy);
    sg.pd = __ldg(a + dy + dx);
    const float2* e = a + dz;
    sg.pe = __ldg(e);
    sg.pg = __ldg(e + dx);
    sg.pf = __ldg(e + dy);
    sg.ph = __ldg(e + dy + dx);
}

__device__ __forceinline__ float2 stage_math(const Stage& sg)
{
    const float px = sg.px, py = sg.py, pz = sg.pz;

    // float-path floor/clamp: exact for this value range (~[-13, 141]);
    // matches the load phase's int path bit-for-bit.
    const float fxf = floorf(px);
    const float fyf = floorf(py);
    const float fzf = floorf(pz);

    const float x0f = fminf(fmaxf(fxf,        0.0f), 127.0f);
    const float x1f = fminf(fmaxf(fxf + 1.0f, 0.0f), 127.0f);
    const float y0f = fminf(fmaxf(fyf,        0.0f), 127.0f);
    const float y1f = fminf(fmaxf(fyf + 1.0f, 0.0f), 127.0f);
    const float z0f = fminf(fmaxf(fzf,        0.0f), 127.0f);
    const float z1f = fminf(fmaxf(fzf + 1.0f, 0.0f), 127.0f);

    const float wx1 = x1f - px, wx0 = px - x0f;
    const float wy1 = y1f - py, wy0 = py - y0f;
    const float wzA = z1f - pz;            // near slab (z1f - z)
    const float wzB = z1f - z0f;           // far slab  (z1f - z0f) — ref convention

    float2 r;
    r.x = wzA * (wy1 * fmaf(wx1, sg.pa.x, wx0 * sg.pc.x)
               + wy0 * fmaf(wx1, sg.pb.x, wx0 * sg.pd.x))
        + wzB * (wy1 * fmaf(wx1, sg.pe.x, wx0 * sg.pg.x)
               + wy0 * fmaf(wx1, sg.pf.x, wx0 * sg.ph.x));
    r.y = wzA * (wy1 * fmaf(wx1, sg.pa.y, wx0 * sg.pc.y)
               + wy0 * fmaf(wx1, sg.pb.y, wx0 * sg.pd.y))
        + wzB * (wy1 * fmaf(wx1, sg.pe.y, wx0 * sg.pg.y)
               + wy0 * fmaf(wx1, sg.pf.y, wx0 * sg.ph.y));
    return r;
}

__global__ __launch_bounds__(256, 5) void st3d_kernel(
    const float* __restrict__ image,   // [B, H, W, D, C] flat, C=2
    float2* __restrict__ out)          // [B*N] float2
{
    __shared__ float2 tile[32][33];

    const int tid  = threadIdx.x;
    const int lane = tid & 31;
    const int wid  = tid >> 5;

    // grid: 4 k-tiles * 4 j-tiles * 128 i * 4 b = 8192 blocks
    const unsigned bx = blockIdx.x;
    const int k0 = (bx & 3) << 5;
    const int j0 = ((bx >> 2) & 3) << 5;
    const int i  = (bx >> 4) & 127;
    const int b  = bx >> 11;

    const float* t = c_theta + b * 12;   // constant-port loads, uniform per block
    const float t0  = t[0],  t1  = t[1],  t2  = t[2],  t3  = t[3];
    const float t4  = t[4],  t5  = t[5],  t6  = t[6],  t7  = t[7];
    const float t8  = t[8],  t9  = t[9],  t10 = t[10], t11 = t[11];

    const float s = 2.0f / 127.0f;
    const float xg = fmaf((float)(j0 + lane), s, -1.0f);   // lane varies x
    const float yg = fmaf((float)i, s, -1.0f);

    const float cx = fmaf(t0, xg, fmaf(t1, yg, t3));
    const float cy = fmaf(t4, xg, fmaf(t5, yg, t7));
    const float cz = fmaf(t8, xg, fmaf(t9, yg, t11));

    const float2* __restrict__ im2 = (const float2*)image + (size_t)b * NPB;

    // 2-deep software pipeline over the 4 k-iterations (kl = wid + 8*it)
    Stage s0, s1;
    stage_load(im2, t2, t6, t10, cx, cy, cz, k0, wid,      s0);
    stage_load(im2, t2, t6, t10, cx, cy, cz, k0, wid + 8,  s1);

    tile[lane][wid]      = stage_math(s0);
    stage_load(im2, t2, t6, t10, cx, cy, cz, k0, wid + 16, s0);

    tile[lane][wid + 8]  = stage_math(s1);
    stage_load(im2, t2, t6, t10, cx, cy, cz, k0, wid + 24, s1);

    tile[lane][wid + 16] = stage_math(s0);
    tile[lane][wid + 24] = stage_math(s1);

    __syncthreads();

    // store phase at float4 granularity: 32 rows x 16 quads = 512 float4;
    // 256 threads x 2. Row jl holds k-contiguous data; STG.128 coalesced.
    float2* __restrict__ op = out + (size_t)b * NPB + i * (WW * DD) + j0 * DD + k0;
    #pragma unroll
    for (int h = 0; h < 2; h++) {
        const int idx  = tid + h * 256;
        const int row  = idx >> 4;          // 0..31 (j_local)
        const int quad = idx & 15;          // 0..15 (pair of k)
        const float2 v0 = tile[row][quad * 2];
        const float2 v1 = tile[row][quad * 2 + 1];
        float4 v; v.x = v0.x; v.y = v0.y; v.z = v1.x; v.w = v1.y;
        *(float4*)(op + row * DD + quad * 2) = v;
    }
}

extern "C" void kernel_launch(void* const* d_in, const int* in_sizes, int n_in,
                              void* d_out, int out_size) {
    const float* image = (const float*)d_in[0];
    const float* theta = (const float*)d_in[1];
    float2* out = (float2*)d_out;

    // stage theta into constant memory (D2D async copy: graph-capturable)
    cudaMemcpyToSymbolAsync(c_theta, theta, 48 * sizeof(float), 0,
                            cudaMemcpyDeviceToDevice);
    st3d_kernel<<<8192, 256>>>(image, out);
}

// round 17
// speedup vs baseline: 1.1764x; 1.0078x over previous
#include <cuda_runtime.h>

// SpatialTransformer 3D trilinear resample. B=4, H=W=D=128, C=2, fp32.
//
// R17 = R16 kernel + z-slab register reuse:
//  - each warp handles CONSECUTIVE k (kl = 4*wid + n): the far z-slab payloads
//    (pe..ph @ z1) of point k are address-identical to the near slab
//    (pa..pd @ z0) of point k+1 for ~70-75% of lanes (exact integer test:
//    p00' == p00 + dz && dx'==dx && dy'==dy). Reuse via selects; fresh near
//    loads predicated on !reuse (~27% lane density -> far fewer L1 lines).
//  - theta read via 3x LDG.128 (uniform per block) -- memcpyToSymbol node
//    removed (it cost ~2-4us of serial graph latency in R16)
//  - float4 store phase (R16), smem 32x33 transpose tile, lane varies j (x)
//
// Reference conventions reproduced exactly: full-extent pixel mapping,
// clip-then-float corners, flat index y*W + z*W*H + x, far-slab weight
// (z1f - z0f). Reused payloads are bit-identical to fresh loads (same
// addresses) -> numerics identical to R13/R16 (rel_err 5.270149e-4).

#define HH 128
#define WW 128
#define DD 128
#define NPB (HH * WW * DD)      // 2097152

struct Stage {
    float2 pa, pb, pc, pd, pe, pf, pg, ph;
    float px, py, pz;
    int p00, dx, dy, dz;        // gather geometry (for reuse test)
};

__device__ __forceinline__ void stage_coords(
    float t2, float t6, float t10,
    float cx, float cy, float cz,
    int k, Stage& sg)
{
    const float s = 2.0f / 127.0f;
    const float zg = fmaf((float)k, s, -1.0f);

    const float px = (fmaf(t2,  zg, cx) + 1.0f) * 64.0f;
    const float py = (fmaf(t6,  zg, cy) + 1.0f) * 64.0f;
    const float pz = (fmaf(t10, zg, cz) + 1.0f) * 64.0f;
    sg.px = px; sg.py = py; sg.pz = pz;

    const int fx = __float2int_rd(px);
    const int fy = __float2int_rd(py);
    const int fz = __float2int_rd(pz);

    const int x0 = min(max(fx,     0), WW - 1);
    const int x1 = min(max(fx + 1, 0), WW - 1);
    const int y0 = min(max(fy,     0), HH - 1);
    const int y1 = min(max(fy + 1, 0), HH - 1);
    const int z0 = min(max(fz,     0), DD - 1);
    const int z1 = min(max(fz + 1, 0), DD - 1);

    // reference flat convention: y*W + z*(W*H) + x
    sg.p00 = y0 * WW + z0 * (WW * HH) + x0;
    sg.dx  = x1 - x0;
    sg.dy  = (y1 - y0) * WW;
    sg.dz  = (z1 - z0) * (WW * HH);
}

__device__ __forceinline__ void load_full(const float2* __restrict__ im2, Stage& sg)
{
    const float2* a = im2 + sg.p00;
    sg.pa = __ldg(a);
    sg.pc = __ldg(a + sg.dx);
    sg.pb = __ldg(a + sg.dy);
    sg.pd = __ldg(a + sg.dy + sg.dx);
    const float2* e = a + sg.dz;
    sg.pe = __ldg(e);
    sg.pg = __ldg(e + sg.dx);
    sg.pf = __ldg(e + sg.dy);
    sg.ph = __ldg(e + sg.dy + sg.dx);
}

// Far slab always loaded fresh; near slab loaded only where reuse fails.
__device__ __forceinline__ bool load_partial(
    const float2* __restrict__ im2, const Stage& prev, Stage& cur)
{
    const bool reuse = (cur.p00 == prev.p00 + prev.dz)
                    && (cur.dx == prev.dx) && (cur.dy == prev.dy);
    const float2* a = im2 + cur.p00;
    if (!reuse) {
        cur.pa = __ldg(a);
        cur.pc = __ldg(a + cur.dx);
        cur.pb = __ldg(a + cur.dy);
        cur.pd = __ldg(a + cur.dy + cur.dx);
    }
    const float2* e = a + cur.dz;
    cur.pe = __ldg(e);
    cur.pg = __ldg(e + cur.dx);
    cur.pf = __ldg(e + cur.dy);
    cur.ph = __ldg(e + cur.dy + cur.dx);
    return reuse;
}

__device__ __forceinline__ void apply_reuse(const Stage& prev, Stage& cur, bool reuse)
{
    if (reuse) {                 // selects: prev far slab -> cur near slab
        cur.pa = prev.pe;  cur.pb = prev.pf;
        cur.pc = prev.pg;  cur.pd = prev.ph;
    }
}

__device__ __forceinline__ float2 stage_math(const Stage& sg)
{
    const float px = sg.px, py = sg.py, pz = sg.pz;

    // float-path floor/clamp: exact for this value range (~[-13, 141]);
    // matches the coord phase's int path bit-for-bit.
    const float fxf = floorf(px);
    const float fyf = floorf(py);
    const float fzf = floorf(pz);

    const float x0f = fminf(fmaxf(fxf,        0.0f), 127.0f);
    const float x1f = fminf(fmaxf(fxf + 1.0f, 0.0f), 127.0f);
    const float y0f = fminf(fmaxf(fyf,        0.0f), 127.0f);
    const float y1f = fminf(fmaxf(fyf + 1.0f, 0.0f), 127.0f);
    const float z0f = fminf(fmaxf(fzf,        0.0f), 127.0f);
    const float z1f = fminf(fmaxf(fzf + 1.0f, 0.0f), 127.0f);

    const float wx1 = x1f - px, wx0 = px - x0f;
    const float wy1 = y1f - py, wy0 = py - y0f;
    const float wzA = z1f - pz;            // near slab (z1f - z)
    const float wzB = z1f - z0f;           // far slab  (z1f - z0f) — ref convention

    float2 r;
    r.x = wzA * (wy1 * fmaf(wx1, sg.pa.x, wx0 * sg.pc.x)
               + wy0 * fmaf(wx1, sg.pb.x, wx0 * sg.pd.x))
        + wzB * (wy1 * fmaf(wx1, sg.pe.x, wx0 * sg.pg.x)
               + wy0 * fmaf(wx1, sg.pf.x, wx0 * sg.ph.x));
    r.y = wzA * (wy1 * fmaf(wx1, sg.pa.y, wx0 * sg.pc.y)
               + wy0 * fmaf(wx1, sg.pb.y, wx0 * sg.pd.y))
        + wzB * (wy1 * fmaf(wx1, sg.pe.y, wx0 * sg.pg.y)
               + wy0 * fmaf(wx1, sg.pf.y, wx0 * sg.ph.y));
    return r;
}

__global__ __launch_bounds__(256, 4) void st3d_kernel(
    const float* __restrict__ image,   // [B, H, W, D, C] flat, C=2
    const float* __restrict__ theta,   // [B, 3, 4]
    float2* __restrict__ out)          // [B*N] float2
{
    __shared__ float2 tile[32][33];

    const int tid  = threadIdx.x;
    const int lane = tid & 31;
    const int wid  = tid >> 5;

    // grid: 4 k-tiles * 4 j-tiles * 128 i * 4 b = 8192 blocks
    const unsigned bx = blockIdx.x;
    const int k0 = (bx & 3) << 5;
    const int j0 = ((bx >> 2) & 3) << 5;
    const int i  = (bx >> 4) & 127;
    const int b  = bx >> 11;

    // theta: 12 floats, 16B-aligned per batch -> 3 uniform LDG.128
    const float4* th4 = (const float4*)(theta + b * 12);
    const float4 ta = __ldg(th4), tb = __ldg(th4 + 1), tc = __ldg(th4 + 2);
    const float t0 = ta.x, t1 = ta.y, t2 = ta.z, t3 = ta.w;
    const float t4 = tb.x, t5 = tb.y, t6 = tb.z, t7 = tb.w;
    const float t8 = tc.x, t9 = tc.y, t10 = tc.z, t11 = tc.w;

    const float s = 2.0f / 127.0f;
    const float xg = fmaf((float)(j0 + lane), s, -1.0f);   // lane varies x
    const float yg = fmaf((float)i, s, -1.0f);

    const float cx = fmaf(t0, xg, fmaf(t1, yg, t3));
    const float cy = fmaf(t4, xg, fmaf(t5, yg, t7));
    const float cz = fmaf(t8, xg, fmaf(t9, yg, t11));

    const float2* __restrict__ im2 = (const float2*)image + (size_t)b * NPB;

    // warp handles CONSECUTIVE k: kb+0..kb+3 (reuse chain across iterations)
    const int kb = k0 + 4 * wid;

    Stage s0, s1;
    stage_coords(t2, t6, t10, cx, cy, cz, kb + 0, s0);
    load_full(im2, s0);
    stage_coords(t2, t6, t10, cx, cy, cz, kb + 1, s1);
    const bool r1 = load_partial(im2, s0, s1);

    apply_reuse(s0, s1, r1);                 // waits on s0 far loads (math needs them too)
    tile[lane][4 * wid + 0] = stage_math(s0);

    stage_coords(t2, t6, t10, cx, cy, cz, kb + 2, s0);
    const bool r2 = load_partial(im2, s1, s0);
    apply_reuse(s1, s0, r2);
    tile[lane][4 * wid + 1] = stage_math(s1);

    stage_coords(t2, t6, t10, cx, cy, cz, kb + 3, s1);
    const bool r3 = load_partial(im2, s0, s1);
    apply_reuse(s0, s1, r3);
    tile[lane][4 * wid + 2] = stage_math(s0);
    tile[lane][4 * wid + 3] = stage_math(s1);

    __syncthreads();

    // store phase at float4 granularity: 32 rows x 16 quads, 256 threads x 2
    float2* __restrict__ op = out + (size_t)b * NPB + i * (WW * DD) + j0 * DD + k0;
    #pragma unroll
    for (int h = 0; h < 2; h++) {
        const int idx  = tid + h * 256;
        const int row  = idx >> 4;          // 0..31 (j_local)
        const int quad = idx & 15;          // 0..15 (pair of k)
        const float2 v0 = tile[row][quad * 2];
        const float2 v1 = tile[row][quad * 2 + 1];
        float4 v; v.x = v0.x; v.y = v0.y; v.z = v1.x; v.w = v1.y;
        *(float4*)(op + row * DD + quad * 2) = v;
    }
}

extern "C" void kernel_launch(void* const* d_in, const int* in_sizes, int n_in,
                              void* d_out, int out_size) {
    const float* image = (const float*)d_in[0];
    const float* theta = (const float*)d_in[1];
    float2* out = (float2*)d_out;

    st3d_kernel<<<8192, 256>>>(image, theta, out);
}